// round 4
// baseline (speedup 1.0000x reference)
#include <cuda_runtime.h>
#include <cuda_fp16.h>
#include <math.h>

#define FEAT 32
#define NA 64
#define NE 32
#define WARPS 8
#define BLK 256

// fp16 e-pair grid: g_pair[a][e][f] = {v[f][a][e], v[f][a][min(e+1,NE-1)]}
// One (a,e) column = 32 half2 = 128B.
__device__ __half2 g_pair[NA * NE * FEAT];
__device__ float g_ticks_az[NA];
__device__ float g_ticks_el[NE];
__device__ float g_consts[4];  // inv_so_az, inv_so_el, omega_az, omega_el

__global__ void prep_kernel(const float* __restrict__ grid) {
    int idx = blockIdx.x * blockDim.x + threadIdx.x;
    if (idx == 0) {
        double oaz = 2.0 * M_PI / (double)NA;
        double oel = M_PI / (double)(NE + 1);
        g_consts[0] = (float)(1.0 / sin(oaz));
        g_consts[1] = (float)(1.0 / sin(oel));
        g_consts[2] = (float)oaz;
        g_consts[3] = (float)oel;
    }
    if (idx < NA)
        g_ticks_az[idx] = (float)((double)idx * (2.0 * M_PI / (double)NA) - M_PI);
    if (idx < NE)
        g_ticks_el[idx] = (float)((double)(idx + 1) * (M_PI / (double)(NE + 1)) - M_PI / 2.0);
    if (idx < FEAT * NA * NE) {
        // idx -> (a, e, f)
        int a = idx >> 10;          // / (NE*FEAT)
        int e = (idx >> 5) & 31;
        int f = idx & 31;
        int e1 = min(e + 1, NE - 1);
        float v0 = grid[(((f << 6) + a) << 5) + e];
        float v1 = grid[(((f << 6) + a) << 5) + e1];
        g_pair[idx] = __floats2half2_rn(v0, v1);
    }
}

__global__ void __launch_bounds__(BLK)
interp_kernel(const float* __restrict__ pts,
              const float* __restrict__ poles,
              float* __restrict__ out, int n) {
    __shared__ float  s_ta[NA];
    __shared__ float  s_te[NE];
    __shared__ float  s_pole[2][FEAT];
    __shared__ float  s_c[4];
    __shared__ float4 s_cf[WARPS][32];       // {cxl, cyl, cxr, cyr}
    __shared__ float4 s_pk[WARPS][32];       // {offs(2x16b), ps, pn, 0}
    __shared__ float  s_tile[WARPS][32][36]; // point-major [p][f], stride 36

    const int t    = threadIdx.x;
    const int warp = t >> 5;
    const int lane = t & 31;

    if (t < NA) s_ta[t] = g_ticks_az[t];
    if (t < NE) s_te[t] = g_ticks_el[t];
    if (t < 2 * FEAT) s_pole[t & 1][t >> 1] = poles[t];  // poles layout (F,2)
    if (t < 4) s_c[t] = g_consts[t];
    __syncthreads();

    const int base = blockIdx.x * BLK + warp * 32;

    // ---------- Phase 1: per-lane point -> coeffs + packed column offsets ----
    {
        int ip = base + lane;
        int ic = min(ip, n - 1);
        float az = pts[ic];
        float el = pts[n + ic];

        const float inv_so_az = s_c[0];
        const float inv_so_el = s_c[1];
        const float omega_az  = s_c[2];
        const float omega_el  = s_c[3];

        // azimuth searchsorted(side='left')
        int r = (int)((az + 3.14159274101257324f) / omega_az);
        r = min(max(r, 0), NA);
        while (r < NA && s_ta[r] < az) ++r;
        while (r > 0 && s_ta[r - 1] >= az) --r;
        int ar = (r >= NA) ? 0 : r;
        int al = (r - 1 < 0) ? (NA - 1) : (r - 1);
        float theta_a = az - s_ta[al];
        float w1a = sinf(omega_az - theta_a) * inv_so_az;
        float w2a = sinf(theta_a) * inv_so_az;

        // elevation searchsorted
        int q = (int)((el + 1.57079637050628662f) / omega_el);
        q = min(max(q, 0), NE);
        while (q < NE && s_te[q] < el) ++q;
        while (q > 0 && s_te[q - 1] >= el) --q;
        bool south = (q == 0);
        bool north = (q == NE);
        int eil = min(max(q - 1, 0), NE - 1);
        float bse = south ? -1.57079632679489662f : s_te[eil];
        float theta_e = el - bse;
        float w1e = sinf(omega_el - theta_e) * inv_so_el;
        float w2e = sinf(theta_e) * inv_so_el;

        // Map slerp weights onto pair slots.
        // interior: pair = (bottom, top); south: pair.x = top ring (eil=eir=0);
        // north: pair.x = bottom ring (eil=eir=NE-1); unused slots get 0.
        float ex = south ? w2e : w1e;
        float ey = (south || north) ? 0.0f : w2e;
        float ps = south ? w1e : 0.0f;
        float pn = north ? w2e : 0.0f;

        unsigned ol = (unsigned)(((al << 5) + eil) << 5);
        unsigned orr = (unsigned)(((ar << 5) + eil) << 5);

        s_cf[warp][lane] = make_float4(ex * w1a, ey * w1a, ex * w2a, ey * w2a);
        s_pk[warp][lane] = make_float4(__uint_as_float(ol | (orr << 16)), ps, pn, 0.0f);
    }
    __syncwarp();

    // ---------- Phase 2: warp-cooperative gather (lane = feature) ----------
    const float pole_s = s_pole[0][lane];
    const float pole_n = s_pole[1][lane];
    const __half2* __restrict__ gp = g_pair;

#pragma unroll 4
    for (int p = 0; p < 32; ++p) {
        float4 pk = s_pk[warp][p];
        float4 cf = s_cf[warp][p];
        unsigned oo = __float_as_uint(pk.x);
        __half2 hl = gp[(oo & 0xFFFFu) + lane];
        __half2 hr = gp[(oo >> 16)    + lane];
        float2 fl = __half22float2(hl);
        float2 fr = __half22float2(hr);
        float res = pk.y * pole_s;
        res = fmaf(pk.z, pole_n, res);
        res = fmaf(cf.x, fl.x, res);
        res = fmaf(cf.y, fl.y, res);
        res = fmaf(cf.z, fr.x, res);
        res = fmaf(cf.w, fr.y, res);
        s_tile[warp][p][lane] = res;   // banks (4p+lane)%32 distinct: conflict-free
    }
    __syncwarp();

    // ---------- Phase 3: LDS.128 (conflict-free) + coalesced scalar STG ------
    int ip = base + lane;
    if (ip < n) {
#pragma unroll
        for (int j = 0; j < 8; ++j) {
            float4 v = *(const float4*)&s_tile[warp][lane][4 * j];
            out[(size_t)(4 * j + 0) * n + ip] = v.x;
            out[(size_t)(4 * j + 1) * n + ip] = v.y;
            out[(size_t)(4 * j + 2) * n + ip] = v.z;
            out[(size_t)(4 * j + 3) * n + ip] = v.w;
        }
    }
}

extern "C" void kernel_launch(void* const* d_in, const int* in_sizes, int n_in,
                              void* d_out, int out_size) {
    const float* pts   = (const float*)d_in[0];  // (2, N)
    const float* grid  = (const float*)d_in[1];  // (32, 64, 32)
    const float* poles = (const float*)d_in[2];  // (32, 2)
    float* out = (float*)d_out;                  // (32, N)
    int n = in_sizes[0] / 2;

    prep_kernel<<<(FEAT * NA * NE + 255) / 256, 256>>>(grid);
    interp_kernel<<<(n + BLK - 1) / BLK, BLK>>>(pts, poles, out, n);
}

// round 5
// speedup vs baseline: 1.1737x; 1.1737x over previous
#include <cuda_runtime.h>
#include <cuda_fp16.h>
#include <math.h>

#define FEAT 32
#define NA 64
#define NE 32
#define NL 33           // pair levels L = 0..NE ; pair(L) = (v[L], v[L+1])
#define WARPS 8
#define BLK 256

// Extended fp16 pair table, column (a, L) = 32 half2 = 128B contiguous.
// v[0] = south pole, v[k] = ring k-1 (k=1..NE), v[NE+1] = north pole.
__device__ __half2 g_pair[NA * NL * FEAT];
__device__ float g_ticks_az[NA];
__device__ float g_ticks_el[NE];
__device__ float g_consts[4];  // inv_so_az, inv_so_el, omega_az, omega_el

__global__ void prep_kernel(const float* __restrict__ grid,
                            const float* __restrict__ poles) {
    int idx = blockIdx.x * blockDim.x + threadIdx.x;
    if (idx == 0) {
        double oaz = 2.0 * M_PI / (double)NA;
        double oel = M_PI / (double)(NE + 1);
        g_consts[0] = (float)(1.0 / sin(oaz));
        g_consts[1] = (float)(1.0 / sin(oel));
        g_consts[2] = (float)oaz;
        g_consts[3] = (float)oel;
    }
    if (idx < NA)
        g_ticks_az[idx] = (float)((double)idx * (2.0 * M_PI / (double)NA) - M_PI);
    if (idx < NE)
        g_ticks_el[idx] = (float)((double)(idx + 1) * (M_PI / (double)(NE + 1)) - M_PI / 2.0);
    if (idx < NA * NL * FEAT) {
        int f = idx & 31;
        int L = (idx >> 5) % NL;
        int a = (idx >> 5) / NL;
        float x = (L == 0)  ? poles[2 * f]     : grid[(((f << 6) + a) << 5) + (L - 1)];
        float y = (L == NE) ? poles[2 * f + 1] : grid[(((f << 6) + a) << 5) + L];
        g_pair[idx] = __floats2half2_rn(x, y);
    }
}

__global__ void __launch_bounds__(BLK, 5)
interp_kernel(const float* __restrict__ pts,
              float* __restrict__ out, int n) {
    __shared__ float  s_ta[NA];
    __shared__ float  s_te[NE];
    __shared__ float  s_c[4];
    __shared__ float4 s_cf[WARPS][32];        // 4 bilinear coeffs
    __shared__ uint2  s_off[WARPS][32];       // byte offsets of 2 columns
    __shared__ float  s_tile[WARPS][32][36];  // point-major [p][f], stride 36

    const int t    = threadIdx.x;
    const int warp = t >> 5;
    const int lane = t & 31;

    if (t < NA) s_ta[t] = g_ticks_az[t];
    if (t < NE) s_te[t] = g_ticks_el[t];
    if (t < 4)  s_c[t]  = g_consts[t];
    __syncthreads();

    const int base = blockIdx.x * BLK + warp * 32;

    // ---------- Phase 1: per-lane point -> 4 coeffs + 2 column offsets ------
    {
        int ip = base + lane;
        int ic = min(ip, n - 1);
        float az = pts[ic];
        float el = pts[n + ic];

        const float inv_so_az = s_c[0];
        const float inv_so_el = s_c[1];
        const float omega_az  = s_c[2];
        const float omega_el  = s_c[3];

        // azimuth searchsorted(side='left')
        int r = (int)((az + 3.14159274101257324f) / omega_az);
        r = min(max(r, 0), NA);
        while (r < NA && s_ta[r] < az) ++r;
        while (r > 0 && s_ta[r - 1] >= az) --r;
        int ar = (r >= NA) ? 0 : r;
        int al = (r - 1 < 0) ? (NA - 1) : (r - 1);
        float theta_a = az - s_ta[al];
        float w1a = __sinf(omega_az - theta_a) * inv_so_az;
        float w2a = __sinf(theta_a) * inv_so_az;

        // elevation searchsorted -> level q in [0, NE]
        int q = (int)((el + 1.57079637050628662f) / omega_el);
        q = min(max(q, 0), NE);
        while (q < NE && s_te[q] < el) ++q;
        while (q > 0 && s_te[q - 1] >= el) --q;
        bool south = (q == 0);
        bool north = (q == NE);
        float bse = south ? -1.57079632679489662f : s_te[q - 1];
        float theta_e = el - bse;
        float w1e = __sinf(omega_el - theta_e) * inv_so_el;
        float w2e = __sinf(theta_e) * inv_so_el;

        // pole rows appear in BOTH azimuth columns -> renormalize that weight
        float s  = w1a + w2a;
        float wx = south ? __fdividef(w1e, s) : w1e;
        float wy = north ? __fdividef(w2e, s) : w2e;

        unsigned col_l = (unsigned)(al * NL + q);
        unsigned col_r = (unsigned)(ar * NL + q);

        s_cf[warp][lane]  = make_float4(wx * w1a, wy * w1a, wx * w2a, wy * w2a);
        s_off[warp][lane] = make_uint2(col_l << 7, col_r << 7);  // byte offsets
    }
    __syncwarp();

    // ---------- Phase 2: warp-cooperative gather (lane = feature) -----------
    const char* __restrict__ gp = (const char*)g_pair;

#pragma unroll 4
    for (int p = 0; p < 32; ++p) {
        uint2  oo = s_off[warp][p];
        float4 cf = s_cf[warp][p];
        __half2 hl = ((const __half2*)(gp + oo.x))[lane];
        __half2 hr = ((const __half2*)(gp + oo.y))[lane];
        float2 fl = __half22float2(hl);
        float2 fr = __half22float2(hr);
        float res = cf.x * fl.x;
        res = fmaf(cf.y, fl.y, res);
        res = fmaf(cf.z, fr.x, res);
        res = fmaf(cf.w, fr.y, res);
        s_tile[warp][p][lane] = res;   // bank (4p+lane)%32 distinct: conflict-free
    }
    __syncwarp();

    // ---------- Phase 3: LDS.128 (conflict-free) + coalesced scalar STG -----
    int ip = base + lane;
    if (ip < n) {
        float* o = out + ip;
        const size_t sn = (size_t)n;
#pragma unroll
        for (int j = 0; j < 8; ++j) {
            float4 v = *(const float4*)&s_tile[warp][lane][4 * j];
            o[0] = v.x; o += sn;
            o[0] = v.y; o += sn;
            o[0] = v.z; o += sn;
            o[0] = v.w; o += sn;
        }
    }
}

extern "C" void kernel_launch(void* const* d_in, const int* in_sizes, int n_in,
                              void* d_out, int out_size) {
    const float* pts   = (const float*)d_in[0];  // (2, N)
    const float* grid  = (const float*)d_in[1];  // (32, 64, 32)
    const float* poles = (const float*)d_in[2];  // (32, 2)
    float* out = (float*)d_out;                  // (32, N)
    int n = in_sizes[0] / 2;

    prep_kernel<<<(NA * NL * FEAT + 255) / 256, 256>>>(grid, poles);
    interp_kernel<<<(n + BLK - 1) / BLK, BLK>>>(pts, out, n);
}

// round 7
// speedup vs baseline: 1.4983x; 1.2766x over previous
#include <cuda_runtime.h>
#include <cuda_fp16.h>
#include <math.h>

#define FEAT 32
#define NA 64
#define NE 32
#define NL 33           // elevation levels L = 0..NE ; quad(L) = levels (L, L+1) incl. poles
#define WARPS 4
#define BLK 128

// Quad table: for azimuth edge al (columns al, al+1 mod NA) and level q:
// g_quad[((al*NL+q)*32 + f)] = {left.lo, left.hi, right.lo, right.hi} = 8 bytes.
// One (al,q) column = 32 * 8B = 256B.
__device__ __half2 g_quad[NA * NL * FEAT * 2];
__device__ float g_ticks_az[NA];
__device__ float g_ticks_el[NE];
__device__ float g_consts[4];  // inv_so_az, inv_so_el, omega_az, omega_el

__global__ void prep_kernel(const float* __restrict__ grid,
                            const float* __restrict__ poles) {
    int idx = blockIdx.x * blockDim.x + threadIdx.x;
    if (idx == 0) {
        double oaz = 2.0 * M_PI / (double)NA;
        double oel = M_PI / (double)(NE + 1);
        g_consts[0] = (float)(1.0 / sin(oaz));
        g_consts[1] = (float)(1.0 / sin(oel));
        g_consts[2] = (float)oaz;
        g_consts[3] = (float)oel;
    }
    if (idx < NA)
        g_ticks_az[idx] = (float)((double)idx * (2.0 * M_PI / (double)NA) - M_PI);
    if (idx < NE)
        g_ticks_el[idx] = (float)((double)(idx + 1) * (M_PI / (double)(NE + 1)) - M_PI / 2.0);
    if (idx < NA * NL * FEAT) {
        int f = idx & 31;
        int c = idx >> 5;
        int q = c % NL;
        int al = c / NL;
        int ar = (al + 1) & (NA - 1);
        float xl = (q == 0)  ? poles[2 * f]     : grid[(((f << 6) + al) << 5) + (q - 1)];
        float yl = (q == NE) ? poles[2 * f + 1] : grid[(((f << 6) + al) << 5) + q];
        float xr = (q == 0)  ? poles[2 * f]     : grid[(((f << 6) + ar) << 5) + (q - 1)];
        float yr = (q == NE) ? poles[2 * f + 1] : grid[(((f << 6) + ar) << 5) + q];
        g_quad[2 * idx]     = __floats2half2_rn(xl, yl);
        g_quad[2 * idx + 1] = __floats2half2_rn(xr, yr);
    }
}

__global__ void __launch_bounds__(BLK, 8)
interp_kernel(const float* __restrict__ pts,
              float* __restrict__ out, int n) {
    __shared__ float  s_ta[NA];
    __shared__ float  s_te[NE];
    __shared__ float  s_c[4];
    __shared__ float4 s_cf[WARPS][32];        // 4 bilinear coeffs (fp32)
    __shared__ float  s_tile[WARPS][32][36];  // point-major [p][f], stride 36

    const int t    = threadIdx.x;
    const int warp = t >> 5;
    const int lane = t & 31;

    if (t < NA) s_ta[t] = g_ticks_az[t];
    if (t < NE) s_te[t] = g_ticks_el[t];
    if (t < 4)  s_c[t]  = g_consts[t];
    __syncthreads();

    const int base = blockIdx.x * BLK + warp * 32;

    // ---------- Phase 1: per-lane point -> 4 coeffs (smem) + offset (reg) ----
    unsigned my_off;
    {
        int ip = base + lane;
        int ic = min(ip, n - 1);
        float az = pts[ic];
        float el = pts[n + ic];

        const float inv_so_az = s_c[0];
        const float inv_so_el = s_c[1];
        const float omega_az  = s_c[2];
        const float omega_el  = s_c[3];

        // azimuth searchsorted(side='left')
        int r = (int)((az + 3.14159274101257324f) / omega_az);
        r = min(max(r, 0), NA);
        while (r < NA && s_ta[r] < az) ++r;
        while (r > 0 && s_ta[r - 1] >= az) --r;
        int al = (r - 1 < 0) ? (NA - 1) : (r - 1);   // ar == (al+1) mod NA always
        float theta_a = az - s_ta[al];
        float w1a = __sinf(omega_az - theta_a) * inv_so_az;
        float w2a = __sinf(theta_a) * inv_so_az;

        // elevation searchsorted -> level q in [0, NE]
        int q = (int)((el + 1.57079637050628662f) / omega_el);
        q = min(max(q, 0), NE);
        while (q < NE && s_te[q] < el) ++q;
        while (q > 0 && s_te[q - 1] >= el) --q;
        bool south = (q == 0);
        bool north = (q == NE);
        float bse = south ? -1.57079632679489662f : s_te[q - 1];
        float theta_e = el - bse;
        float w1e = __sinf(omega_el - theta_e) * inv_so_el;
        float w2e = __sinf(theta_e) * inv_so_el;

        // pole rows appear in BOTH azimuth columns -> renormalize that weight
        float s  = w1a + w2a;
        float wx = south ? __fdividef(w1e, s) : w1e;
        float wy = north ? __fdividef(w2e, s) : w2e;

        s_cf[warp][lane] = make_float4(wx * w1a, wy * w1a, wx * w2a, wy * w2a);
        my_off = (unsigned)(al * NL + q) << 8;   // byte offset of 256B column
    }
    __syncwarp();

    // ---------- Phase 2: warp-cooperative gather (lane = feature) -----------
    const char* __restrict__ gq = (const char*)g_quad;

#pragma unroll 4
    for (int p = 0; p < 32; ++p) {
        unsigned off = __shfl_sync(0xffffffffu, my_off, p);
        float4 cf = s_cf[warp][p];
        uint2 q2 = *(const uint2*)(gq + off + 8 * lane);   // single LDG.64
        float2 fl = __half22float2(*(const __half2*)&q2.x);
        float2 fr = __half22float2(*(const __half2*)&q2.y);
        float res = cf.x * fl.x;
        res = fmaf(cf.y, fl.y, res);
        res = fmaf(cf.z, fr.x, res);
        res = fmaf(cf.w, fr.y, res);
        s_tile[warp][p][lane] = res;   // banks (4p+lane)%32 distinct: conflict-free
    }
    __syncwarp();

    // ---------- Phase 3: per-lane LDS.128 (aligned, conflict-free) + STG ----
    int ip = base + lane;
    if (ip < n) {
        float* o = out + ip;
        const size_t sn = (size_t)n;
#pragma unroll
        for (int j = 0; j < 8; ++j) {
            float4 v = *(const float4*)&s_tile[warp][lane][4 * j];
            o[0] = v.x; o += sn;
            o[0] = v.y; o += sn;
            o[0] = v.z; o += sn;
            o[0] = v.w; o += sn;
        }
    }
}

extern "C" void kernel_launch(void* const* d_in, const int* in_sizes, int n_in,
                              void* d_out, int out_size) {
    const float* pts   = (const float*)d_in[0];  // (2, N)
    const float* grid  = (const float*)d_in[1];  // (32, 64, 32)
    const float* poles = (const float*)d_in[2];  // (32, 2)
    float* out = (float*)d_out;                  // (32, N)
    int n = in_sizes[0] / 2;

    prep_kernel<<<(NA * NL * FEAT + 255) / 256, 256>>>(grid, poles);
    interp_kernel<<<(n + BLK - 1) / BLK, BLK>>>(pts, out, n);
}